// round 5
// baseline (speedup 1.0000x reference)
#include <cuda_runtime.h>
#include <cuda_fp16.h>
#include <cstdint>
#include <cstddef>

#define BATCH   32
#define NVARS   16
#define SAMPLES 4096
#define EMB     128
#define SPAD    4128      // padded sample rows (max needed s = 4123)
#define NTOK    1016
#define NST     64        // 2 planes (q1,q2) * 32 window positions, K=128 bytes each

// Scratch (device globals: allocation-free rule)
__device__ __align__(1024) int8_t g_enc[(size_t)BATCH * SPAD * EMB];   // 16.9 MB
__device__ __align__(1024) int8_t g_q[2ull * 128 * 4096];              // q[plane][n][k], 1 MB
__device__ float g_s[128];                                             // s1[n]/256

// ======================= helpers =======================
__device__ __forceinline__ uint32_t smem_u32(const void* p) {
    uint32_t a;
    asm("{ .reg .u64 t; cvta.to.shared.u64 t, %1; cvt.u32.u64 %0, t; }" : "=r"(a) : "l"(p));
    return a;
}
#define CP16(dst, src) \
    asm volatile("cp.async.cg.shared.global [%0], [%1], 16;" :: "r"(dst), "l"(src))
#define CP_COMMIT()  asm volatile("cp.async.commit_group;" ::: "memory")
#define CP_WAIT(n)   asm volatile("cp.async.wait_group %0;" :: "n"(n) : "memory")

#define LDSM4(r, addr) \
    asm volatile("ldmatrix.sync.aligned.m8n8.x4.shared.b16 {%0,%1,%2,%3}, [%4];" \
        : "=r"((r)[0]), "=r"((r)[1]), "=r"((r)[2]), "=r"((r)[3]) : "r"(addr))

#define MMAI8(d, a, b0, b1) \
    asm volatile("mma.sync.aligned.m16n8k32.row.col.s32.s8.s8.s32 " \
        "{%0,%1,%2,%3}, {%4,%5,%6,%7}, {%8,%9}, {%0,%1,%2,%3};" \
        : "+r"((d)[0]), "+r"((d)[1]), "+r"((d)[2]), "+r"((d)[3]) \
        : "r"((a)[0]), "r"((a)[1]), "r"((a)[2]), "r"((a)[3]), "r"(b0), "r"(b1))

// ======================= Kernel 1: fused W-quantize + encode =======================
// Blocks [0,128):  per-column int8 two-plane quantization of W_patch
// Blocks [128,..): encode: enc[b,s,d] = clamp(floor(sum_v x*Ws + bs)), int8
#define PREP_BLOCKS 128
#define ENC_SBLK    258          // SPAD/16

__global__ void __launch_bounds__(256, 3)
prep_encode_kernel(const float* __restrict__ x,
                   const float* __restrict__ Ws,
                   const float* __restrict__ bs,
                   const float* __restrict__ Wp) {
    __shared__ float red[8];
    __shared__ float xs[NVARS][16];
    int tid = threadIdx.x;
    int bx = blockIdx.x;

    if (bx < PREP_BLOCKS) {
        // ---- quantize column n of W_patch into planes q1, q2 ----
        int n = bx;
        float w[16];
        float m = 0.f;
#pragma unroll
        for (int i = 0; i < 16; i++) {
            w[i] = Wp[(size_t)(tid + i * 256) * 128 + n];
            m = fmaxf(m, fabsf(w[i]));
        }
#pragma unroll
        for (int o = 16; o; o >>= 1) m = fmaxf(m, __shfl_xor_sync(~0u, m, o));
        if ((tid & 31) == 0) red[tid >> 5] = m;
        __syncthreads();
        float mx = red[0];
#pragma unroll
        for (int j = 1; j < 8; j++) mx = fmaxf(mx, red[j]);
        float s1  = (mx > 0.f) ? mx * (1.f / 126.f) : 1.f;
        float inv = (mx > 0.f) ? 126.f / mx : 0.f;
#pragma unroll
        for (int i = 0; i < 16; i++) {
            int k = tid + i * 256;
            float q1f = rintf(w[i] * inv);                 // |q1f| <= 126
            float r = w[i] - s1 * q1f;
            float q2f = rintf(r * inv * 256.f);            // |.| <= 128
            q2f = fminf(127.f, fmaxf(-127.f, q2f));
            g_q[(size_t)n * 4096 + k]          = (int8_t)q1f;
            g_q[524288 + (size_t)n * 4096 + k] = (int8_t)q2f;
        }
        if (tid == 0) g_s[n] = s1 * (1.f / 256.f);
    } else {
        // ---- encode: 16 samples ----
        int idx = bx - PREP_BLOCKS;
        int b = idx / ENC_SBLK;
        int s0 = (idx - b * ENC_SBLK) * 16;
        {
            int v = tid >> 4, s = tid & 15;
            int sg = s0 + s;
            xs[v][s] = (sg < SAMPLES) ? x[((size_t)b * NVARS + v) * SAMPLES + sg] : 0.f;
        }
        __syncthreads();
        int d = tid & 127;
        int sh = (tid >> 7) * 8;
        float wv[NVARS];
#pragma unroll
        for (int v = 0; v < NVARS; v++) wv[v] = Ws[v * EMB + d];
        float bias = bs[d];
#pragma unroll
        for (int s = 0; s < 8; s++) {
            int sg = s0 + sh + s;
            float acc = bias;
#pragma unroll
            for (int v = 0; v < NVARS; v++) acc += xs[v][sh + s] * wv[v];
            float val = (sg < SAMPLES) ? floorf(acc) : 0.f;
            val = fminf(127.f, fmaxf(-127.f, val));        // |enc| < ~30 in practice
            g_enc[((size_t)b * SPAD + sg) * EMB + d] = (int8_t)val;
        }
    }
}

// ======================= Kernel 2: windowed GEMM (int8 IMMA, batch-paired) =======================
// CTA tile: M=256 (128 tokens of batch b + 128 tokens of batch b+16), N=128.
// 64 stages: plane = it>>5 (q1 then q2), w = it&31; stage K = 128 int8.
// Single s32 accumulator; acc *= 256 at the plane boundary (exact).
// Stage smem: A 256x128B (32KB) + B 128x128B (16KB) = 48KB; double buffered.
// Rows are 128B (8 x 16B chunks), XOR swizzle chunk' = c ^ (row&7).
#define SM_A  1024u
#define SM_B  33792u
#define STAGE_STRIDE 49152u
#define SMEM_BYTES (1024 + 2 * 49152)

__global__ void __launch_bounds__(256, 1)
gemm_kernel(const float* __restrict__ bp, float* __restrict__ out) {
    extern __shared__ char smem[];
    uint32_t sb = smem_u32(smem);
    int tid = threadIdx.x, wid = tid >> 5, lid = tid & 31;
    int t0 = blockIdx.x * 128;
    int b  = blockIdx.y;            // pair (b, b+16)

    if (tid < 128) {
        ((float*)smem)[tid]         = g_s[tid];   // column scales
        ((float*)(smem + 512))[tid] = bp[tid];    // bias
    }

    int acc[4][8][4];
#pragma unroll
    for (int i = 0; i < 4; i++)
#pragma unroll
        for (int j = 0; j < 8; j++)
#pragma unroll
            for (int k = 0; k < 4; k++) acc[i][j][k] = 0;

    // ---- producer addressing ----
    int prow = tid >> 3, pc = tid & 7;              // base row (0..31), 16B chunk
    const int8_t* aLo = g_enc + ((size_t)b * SPAD + (size_t)t0 * 4) * 128
                        + (size_t)prow * 512 + pc * 16;
    const int8_t* aHi = aLo + (size_t)16 * SPAD * 128;   // batch b+16
    const int8_t* bPt = g_q + (size_t)prow * 4096 + pc * 16;
    uint32_t pdst = (uint32_t)prow * 128 + (uint32_t)((pc ^ (prow & 7)) << 4);

    auto fill = [&](int it, int buf) {
        int plane = it >> 5, w = it & 31;
        uint32_t st = buf * STAGE_STRIDE;
        size_t offA = (size_t)w * 128;
        size_t offB = (size_t)plane * 524288 + (size_t)w * 128;
#pragma unroll
        for (int r = 0; r < 4; r++)   // A rows 0..127 (batch b)
            CP16(sb + SM_A + st + pdst + r * 4096u, (const void*)(aLo + offA + (size_t)r * 16384));
#pragma unroll
        for (int r = 0; r < 4; r++)   // A rows 128..255 (batch b+16)
            CP16(sb + SM_A + st + 16384u + pdst + r * 4096u, (const void*)(aHi + offA + (size_t)r * 16384));
#pragma unroll
        for (int r = 0; r < 4; r++)   // B plane
            CP16(sb + SM_B + st + pdst + r * 4096u, (const void*)(bPt + offB + (size_t)r * 131072));
        CP_COMMIT();
    };

    // ---- consumer addressing (warp tile 64m x 64n; warp grid 4x2) ----
    int wr = wid & 3, wc = wid >> 2;
    uint32_t xorv = (uint32_t)(lid & 7);
    uint32_t aRowOff[4], bRowOff[4];
#pragma unroll
    for (int mi = 0; mi < 4; mi++)
        aRowOff[mi] = (uint32_t)(wr * 64 + mi * 16 + (lid & 15)) * 128;
#pragma unroll
    for (int p = 0; p < 4; p++)
        bRowOff[p] = (uint32_t)(wc * 64 + p * 16 + (lid & 7) + ((lid & 16) ? 8 : 0)) * 128;
    uint32_t cbA = (uint32_t)(lid >> 4);
    uint32_t cbB = (uint32_t)((lid >> 3) & 1);

    auto compute = [&](int buf) {
        uint32_t st = buf * STAGE_STRIDE;
        uint32_t baseA = sb + SM_A + st, baseB = sb + SM_B + st;
#pragma unroll
        for (int kk = 0; kk < 4; kk++) {            // 32 int8 k per kk
            uint32_t aSw = ((2u * kk + cbA) ^ xorv) << 4;
            uint32_t bSw = ((2u * kk + cbB) ^ xorv) << 4;
            uint32_t afr[4][4];
#pragma unroll
            for (int mi = 0; mi < 4; mi++)
                LDSM4(afr[mi], baseA + aRowOff[mi] + aSw);
            uint32_t bfr[4][4];
#pragma unroll
            for (int p = 0; p < 4; p++)
                LDSM4(bfr[p], baseB + bRowOff[p] + bSw);
#pragma unroll
            for (int mi = 0; mi < 4; mi++)
#pragma unroll
                for (int p = 0; p < 4; p++) {
                    MMAI8(acc[mi][2 * p],     afr[mi], bfr[p][0], bfr[p][1]);
                    MMAI8(acc[mi][2 * p + 1], afr[mi], bfr[p][2], bfr[p][3]);
                }
        }
    };

    // ---- double-buffered main loop ----
    fill(0, 0);
    for (int it = 0; it < NST; it++) {
        int buf = it & 1;
        if (it + 1 < NST) {
            fill(it + 1, buf ^ 1);
            CP_WAIT(1);            // stage(it) complete
        } else {
            CP_WAIT(0);
        }
        __syncthreads();
        compute(buf);
        if (it == 31) {            // plane boundary: acc = 256*I1, then accumulate I2
#pragma unroll
            for (int i = 0; i < 4; i++)
#pragma unroll
                for (int j = 0; j < 8; j++)
#pragma unroll
                    for (int k = 0; k < 4; k++) acc[i][j][k] <<= 8;
        }
        __syncthreads();           // guard buffer reuse
    }

    // ---- epilogue: acc*s1[n]/256 + bias, floor, fp32 stores ----
    const float* ssm = (const float*)smem;
    const float* bsm = (const float*)(smem + 512);
    int bOut = b + ((wr >= 2) ? 16 : 0);
    int rloc = (wr & 1) * 64 + (lid >> 2);
    int nb = wc * 64 + (lid & 3) * 2;
#pragma unroll
    for (int mi = 0; mi < 4; mi++) {
        int trow0 = t0 + rloc + mi * 16;
#pragma unroll
        for (int ni = 0; ni < 8; ni++) {
            int n = nb + ni * 8;
            float sx = ssm[n], sy = ssm[n + 1];
            float bx = bsm[n], by = bsm[n + 1];
            if (trow0 < NTOK) {
                float2 v;
                v.x = floorf((float)acc[mi][ni][0] * sx + bx);
                v.y = floorf((float)acc[mi][ni][1] * sy + by);
                *(float2*)(out + ((size_t)bOut * NTOK + trow0) * 128 + n) = v;
            }
            if (trow0 + 8 < NTOK) {
                float2 v;
                v.x = floorf((float)acc[mi][ni][2] * sx + bx);
                v.y = floorf((float)acc[mi][ni][3] * sy + by);
                *(float2*)(out + ((size_t)bOut * NTOK + trow0 + 8) * 128 + n) = v;
            }
        }
    }
}

// ======================= launch =======================
extern "C" void kernel_launch(void* const* d_in, const int* in_sizes, int n_in,
                              void* d_out, int out_size) {
    const float* x  = (const float*)d_in[0];
    const float* Ws = (const float*)d_in[1];
    const float* bs = (const float*)d_in[2];
    const float* Wp = (const float*)d_in[3];
    const float* bp = (const float*)d_in[4];
    float* out = (float*)d_out;

    prep_encode_kernel<<<PREP_BLOCKS + ENC_SBLK * BATCH, 256>>>(x, Ws, bs, Wp);

    cudaFuncSetAttribute(gemm_kernel, cudaFuncAttributeMaxDynamicSharedMemorySize, SMEM_BYTES);
    gemm_kernel<<<dim3(8, 16), 256, SMEM_BYTES>>>(bp, out);

    (void)in_sizes; (void)n_in; (void)out_size;
}

// round 7
// speedup vs baseline: 1.8231x; 1.8231x over previous
#include <cuda_runtime.h>
#include <cuda_fp16.h>
#include <cstdint>
#include <cstddef>

#define BATCH   32
#define NVARS   16
#define SAMPLES 4096
#define EMB     128
#define SPAD    4128      // padded sample rows (max needed s = 4123)
#define NTOK    1016
#define NST     64        // K stages: w2 = w*2 + half, K=64 fp16 each

// Scratch (device globals: allocation-free rule)
__device__ __align__(1024) __half g_enc[(size_t)BATCH * SPAD * EMB];   // ~33.8 MB
__device__ __align__(1024) __half g_wt[2ull * 128 * 4096];             // Wt[pass][n][k], 2 MB

// ======================= helpers =======================
__device__ __forceinline__ uint32_t smem_u32(const void* p) {
    uint32_t a;
    asm("{ .reg .u64 t; cvta.to.shared.u64 t, %1; cvt.u32.u64 %0, t; }" : "=r"(a) : "l"(p));
    return a;
}
#define CP16(dst, src) \
    asm volatile("cp.async.cg.shared.global [%0], [%1], 16;" :: "r"(dst), "l"(src))
#define CP_COMMIT()  asm volatile("cp.async.commit_group;" ::: "memory")
#define CP_WAIT(n)   asm volatile("cp.async.wait_group %0;" :: "n"(n) : "memory")

#define LDSM4(r, addr) \
    asm volatile("ldmatrix.sync.aligned.m8n8.x4.shared.b16 {%0,%1,%2,%3}, [%4];" \
        : "=r"((r)[0]), "=r"((r)[1]), "=r"((r)[2]), "=r"((r)[3]) : "r"(addr))

#define MMA16816(d, a, b0, b1) \
    asm volatile("mma.sync.aligned.m16n8k16.row.col.f32.f16.f16.f32 " \
        "{%0,%1,%2,%3}, {%4,%5,%6,%7}, {%8,%9}, {%0,%1,%2,%3};" \
        : "+f"((d)[0]), "+f"((d)[1]), "+f"((d)[2]), "+f"((d)[3]) \
        : "r"((a)[0]), "r"((a)[1]), "r"((a)[2]), "r"((a)[3]), "r"(b0), "r"(b1))

// ======================= Kernel 1: fused prep_w + encode =======================
// Blocks [0,64):   split+transpose W_patch -> g_wt (64 k-rows x 128 n each)
// Blocks [64,...): encode: enc[b,s,d] = floor(sum_v x*Ws + bs), 16 samples per block
#define PREP_BLOCKS 64
#define ENC_SBLK    258          // SPAD/16

__global__ void __launch_bounds__(256, 3)
prep_encode_kernel(const float* __restrict__ x,
                   const float* __restrict__ Ws,
                   const float* __restrict__ bs,
                   const float* __restrict__ Wp) {
    __shared__ __half tp_h[128][65];
    __shared__ __half tp_l[128][65];
    __shared__ float  xs[NVARS][16];
    int tid = threadIdx.x;
    int bx = blockIdx.x;

    if (bx < PREP_BLOCKS) {
        // ---- W split + transpose: 64 k-rows x 128 n ----
        int k0 = bx * 64;
#pragma unroll 4
        for (int i = 0; i < 32; i++) {
            int idx = tid + i * 256;          // 8192 elems
            int kr = idx >> 7, n = idx & 127;
            float w = Wp[(size_t)(k0 + kr) * 128 + n];
            __half hi = __float2half_rn(w);
            tp_h[n][kr] = hi;
            tp_l[n][kr] = __float2half_rn(w - __half2float(hi));
        }
        __syncthreads();
#pragma unroll 4
        for (int i = 0; i < 32; i++) {
            int idx = tid + i * 256;
            int n = idx >> 6, kr = idx & 63;  // coalesced 64-wide writes
            g_wt[(size_t)n * 4096 + k0 + kr]          = tp_h[n][kr];
            g_wt[524288 + (size_t)n * 4096 + k0 + kr] = tp_l[n][kr];
        }
    } else {
        // ---- encode: 16 samples ----
        int idx = bx - PREP_BLOCKS;
        int b = idx / ENC_SBLK;
        int s0 = (idx - b * ENC_SBLK) * 16;
        {
            int v = tid >> 4, s = tid & 15;
            int sg = s0 + s;
            xs[v][s] = (sg < SAMPLES) ? x[((size_t)b * NVARS + v) * SAMPLES + sg] : 0.f;
        }
        __syncthreads();
        int d = tid & 127;
        int sh = (tid >> 7) * 8;
        float wv[NVARS];
#pragma unroll
        for (int v = 0; v < NVARS; v++) wv[v] = Ws[v * EMB + d];
        float bias = bs[d];
#pragma unroll
        for (int s = 0; s < 8; s++) {
            int sg = s0 + sh + s;
            float acc = bias;
#pragma unroll
            for (int v = 0; v < NVARS; v++) acc += xs[v][sh + s] * wv[v];
            float val = (sg < SAMPLES) ? floorf(acc) : 0.f;
            g_enc[((size_t)b * SPAD + sg) * EMB + d] = __float2half_rn(val);
        }
    }
}

// ======================= Kernel 2: windowed GEMM (batch-paired, 3-stage pipe) =======================
// CTA tile: M=256 (128 tokens of batch b + 128 tokens of batch b+16), N=128.
// 64 stages of K=64; stage smem: A 32KB + Bhi 16KB + Blo 16KB = 64KB; 3 stages.
// One barrier per stage: CP_WAIT(1) -> syncthreads -> fill(it+2) -> compute(it).
// At the wait, only stages it and it+1 can be pending; allowing 1 pending group
// guarantees stage it has landed (fill(it+2) is committed only after the barrier).
// Rows are 128B (8 x 16B chunks), XOR swizzle chunk' = c ^ (row&7).
#define SM_A  1024u
#define SM_BH 33792u
#define SM_BL 50176u
#define STAGE_STRIDE 65536u
#define SMEM_BYTES (1024 + 3 * 65536)

__global__ void __launch_bounds__(256, 1)
gemm_kernel(const float* __restrict__ bp, float* __restrict__ out) {
    extern __shared__ char smem[];
    uint32_t sb = smem_u32(smem);
    int tid = threadIdx.x, wid = tid >> 5, lid = tid & 31;
    int t0 = blockIdx.x * 128;
    int b  = blockIdx.y;            // pair (b, b+16)

    if (tid < 128) ((float*)(smem + 512))[tid] = bp[tid];

    float acc[4][8][4];
#pragma unroll
    for (int i = 0; i < 4; i++)
#pragma unroll
        for (int j = 0; j < 8; j++)
#pragma unroll
            for (int k = 0; k < 4; k++) acc[i][j][k] = 0.f;

    // ---- producer addressing (precomputed; only w2*64 varies per stage) ----
    int prow = tid >> 3, pc = tid & 7;           // producer row (0..31 per r-step), 16B chunk
    const __half* aLo = g_enc + ((size_t)b * SPAD) * 128 + (size_t)t0 * 512
                        + (size_t)prow * 512 + pc * 8;
    const __half* aHi = aLo + (size_t)16 * SPAD * 128;   // batch b+16
    const __half* bPt = g_wt + (size_t)prow * 4096 + pc * 8;
    uint32_t pdst = (uint32_t)prow * 128 + (uint32_t)((pc ^ (prow & 7)) << 4);

    auto fill = [&](int w2, int buf) {
        uint32_t st = (uint32_t)buf * STAGE_STRIDE;
        size_t off = (size_t)w2 * 64;
#pragma unroll
        for (int r = 0; r < 4; r++)   // A rows 0..127 (batch b)
            CP16(sb + SM_A + st + pdst + r * 4096u, (const void*)(aLo + off + (size_t)r * 16384));
#pragma unroll
        for (int r = 0; r < 4; r++)   // A rows 128..255 (batch b+16)
            CP16(sb + SM_A + st + 16384u + pdst + r * 4096u, (const void*)(aHi + off + (size_t)r * 16384));
#pragma unroll
        for (int r = 0; r < 4; r++)   // B hi
            CP16(sb + SM_BH + st + pdst + r * 4096u, (const void*)(bPt + off + (size_t)r * 131072));
#pragma unroll
        for (int r = 0; r < 4; r++)   // B lo
            CP16(sb + SM_BL + st + pdst + r * 4096u, (const void*)(bPt + 524288 + off + (size_t)r * 131072));
        CP_COMMIT();
    };

    // ---- consumer addressing (warp tile 64m x 64n; warp grid 4x2) ----
    int wr = wid & 3, wc = wid >> 2;
    uint32_t xorv = (uint32_t)(lid & 7);
    uint32_t aRowOff[4], bRowOff[4];
#pragma unroll
    for (int mi = 0; mi < 4; mi++)
        aRowOff[mi] = (uint32_t)(wr * 64 + mi * 16 + (lid & 15)) * 128;
#pragma unroll
    for (int p = 0; p < 4; p++)
        bRowOff[p] = (uint32_t)(wc * 64 + p * 16 + (lid & 7) + ((lid & 16) ? 8 : 0)) * 128;
    uint32_t cbA = (uint32_t)(lid >> 4);
    uint32_t cbB = (uint32_t)((lid >> 3) & 1);

    auto compute = [&](int buf) {
        uint32_t st = (uint32_t)buf * STAGE_STRIDE;
        uint32_t baseA = sb + SM_A + st, baseBH = sb + SM_BH + st, baseBL = sb + SM_BL + st;
#pragma unroll
        for (int kk = 0; kk < 4; kk++) {
            uint32_t aSw = ((2u * kk + cbA) ^ xorv) << 4;
            uint32_t bSw = ((2u * kk + cbB) ^ xorv) << 4;
            uint32_t afr[4][4];
#pragma unroll
            for (int mi = 0; mi < 4; mi++)
                LDSM4(afr[mi], baseA + aRowOff[mi] + aSw);
            uint32_t bfr[4][4];
#pragma unroll
            for (int p = 0; p < 4; p++)
                LDSM4(bfr[p], baseBH + bRowOff[p] + bSw);
#pragma unroll
            for (int mi = 0; mi < 4; mi++)
#pragma unroll
                for (int p = 0; p < 4; p++) {
                    MMA16816(acc[mi][2 * p],     afr[mi], bfr[p][0], bfr[p][1]);
                    MMA16816(acc[mi][2 * p + 1], afr[mi], bfr[p][2], bfr[p][3]);
                }
#pragma unroll
            for (int p = 0; p < 4; p++)
                LDSM4(bfr[p], baseBL + bRowOff[p] + bSw);
#pragma unroll
            for (int mi = 0; mi < 4; mi++)
#pragma unroll
                for (int p = 0; p < 4; p++) {
                    MMA16816(acc[mi][2 * p],     afr[mi], bfr[p][0], bfr[p][1]);
                    MMA16816(acc[mi][2 * p + 1], afr[mi], bfr[p][2], bfr[p][3]);
                }
        }
    };

    // ---- 3-stage pipeline, one barrier per stage ----
    fill(0, 0);
    fill(1, 1);
    for (int it = 0; it < NST; it++) {
        int buf = it - (it / 3) * 3;          // it % 3
        if (it + 1 < NST) CP_WAIT(1);         // stage it landed; stage it+1 may be pending
        else CP_WAIT(0);
        __syncthreads();                      // data visible + compute(it-1) retired
        if (it + 2 < NST) {
            int nbuf = buf + 2; if (nbuf >= 3) nbuf -= 3;
            fill(it + 2, nbuf);               // overwrites buffer of compute(it-1): safe
        }
        compute(buf);
    }

    // ---- epilogue: D + b_patch, floor, fp32 stores ----
    const float* bsm = (const float*)(smem + 512);
    int bOut = b + ((wr >= 2) ? 16 : 0);
    int rloc = (wr & 1) * 64 + (lid >> 2);     // row within the 128-token half
    int nb = wc * 64 + (lid & 3) * 2;
#pragma unroll
    for (int mi = 0; mi < 4; mi++) {
        int trow0 = t0 + rloc + mi * 16;
#pragma unroll
        for (int ni = 0; ni < 8; ni++) {
            int n = nb + ni * 8;
            float bx = bsm[n], by = bsm[n + 1];
            if (trow0 < NTOK) {
                float2 v;
                v.x = floorf(acc[mi][ni][0] + bx);
                v.y = floorf(acc[mi][ni][1] + by);
                *(float2*)(out + ((size_t)bOut * NTOK + trow0) * 128 + n) = v;
            }
            if (trow0 + 8 < NTOK) {
                float2 v;
                v.x = floorf(acc[mi][ni][2] + bx);
                v.y = floorf(acc[mi][ni][3] + by);
                *(float2*)(out + ((size_t)bOut * NTOK + trow0 + 8) * 128 + n) = v;
            }
        }
    }
}

// ======================= launch =======================
extern "C" void kernel_launch(void* const* d_in, const int* in_sizes, int n_in,
                              void* d_out, int out_size) {
    const float* x  = (const float*)d_in[0];
    const float* Ws = (const float*)d_in[1];
    const float* bs = (const float*)d_in[2];
    const float* Wp = (const float*)d_in[3];
    const float* bp = (const float*)d_in[4];
    float* out = (float*)d_out;

    prep_encode_kernel<<<PREP_BLOCKS + ENC_SBLK * BATCH, 256>>>(x, Ws, bs, Wp);

    cudaFuncSetAttribute(gemm_kernel, cudaFuncAttributeMaxDynamicSharedMemorySize, SMEM_BYTES);
    gemm_kernel<<<dim3(8, 16), 256, SMEM_BYTES>>>(bp, out);

    (void)in_sizes; (void)n_in; (void)out_size;
}

// round 8
// speedup vs baseline: 3.0492x; 1.6725x over previous
#include <cuda_runtime.h>
#include <cuda_fp16.h>
#include <cstdint>
#include <cstddef>

#define BATCH   32
#define NVARS   16
#define SAMPLES 4096
#define EMB     128
#define SPAD    4128      // padded sample rows (max needed s = 4123)
#define NTOK    1016
#define NST     64        // K stages: w2 = w*2 + half, K=64 fp16 each

// Scratch (device globals: allocation-free rule)
__device__ __align__(1024) __half g_enc[(size_t)BATCH * SPAD * EMB];   // ~33.8 MB
__device__ __align__(1024) __half g_wt[2ull * 128 * 4096];             // Wt[pass][n][k], 2 MB

// ======================= helpers =======================
__device__ __forceinline__ uint32_t smem_u32(const void* p) {
    uint32_t a;
    asm("{ .reg .u64 t; cvta.to.shared.u64 t, %1; cvt.u32.u64 %0, t; }" : "=r"(a) : "l"(p));
    return a;
}
#define CP16(dst, src) \
    asm volatile("cp.async.cg.shared.global [%0], [%1], 16;" :: "r"(dst), "l"(src))
#define CP_COMMIT()  asm volatile("cp.async.commit_group;" ::: "memory")
#define CP_WAIT(n)   asm volatile("cp.async.wait_group %0;" :: "n"(n) : "memory")

#define LDSM4(r, addr) \
    asm volatile("ldmatrix.sync.aligned.m8n8.x4.shared.b16 {%0,%1,%2,%3}, [%4];" \
        : "=r"((r)[0]), "=r"((r)[1]), "=r"((r)[2]), "=r"((r)[3]) : "r"(addr))

#define MMA16816(d, a, b0, b1) \
    asm volatile("mma.sync.aligned.m16n8k16.row.col.f32.f16.f16.f32 " \
        "{%0,%1,%2,%3}, {%4,%5,%6,%7}, {%8,%9}, {%0,%1,%2,%3};" \
        : "+f"((d)[0]), "+f"((d)[1]), "+f"((d)[2]), "+f"((d)[3]) \
        : "r"((a)[0]), "r"((a)[1]), "r"((a)[2]), "r"((a)[3]), "r"(b0), "r"(b1))

// ======================= Kernel 1: fused prep_w + encode =======================
// Blocks [0,64):   split+transpose W_patch -> g_wt (64 k-rows x 128 n each)
// Blocks [64,...): encode: enc[b,s,d] = floor(sum_v x*Ws + bs), 16 samples per block
#define PREP_BLOCKS 64
#define ENC_SBLK    258          // SPAD/16

__global__ void __launch_bounds__(256, 3)
prep_encode_kernel(const float* __restrict__ x,
                   const float* __restrict__ Ws,
                   const float* __restrict__ bs,
                   const float* __restrict__ Wp) {
    __shared__ __half tp_h[128][65];
    __shared__ __half tp_l[128][65];
    __shared__ float  xs[NVARS][16];
    int tid = threadIdx.x;
    int bx = blockIdx.x;

    if (bx < PREP_BLOCKS) {
        // ---- W split + transpose: 64 k-rows x 128 n ----
        int k0 = bx * 64;
#pragma unroll 4
        for (int i = 0; i < 32; i++) {
            int idx = tid + i * 256;          // 8192 elems
            int kr = idx >> 7, n = idx & 127;
            float w = Wp[(size_t)(k0 + kr) * 128 + n];
            __half hi = __float2half_rn(w);
            tp_h[n][kr] = hi;
            tp_l[n][kr] = __float2half_rn(w - __half2float(hi));
        }
        __syncthreads();
#pragma unroll 4
        for (int i = 0; i < 32; i++) {
            int idx = tid + i * 256;
            int n = idx >> 6, kr = idx & 63;  // coalesced 64-wide writes
            g_wt[(size_t)n * 4096 + k0 + kr]          = tp_h[n][kr];
            g_wt[524288 + (size_t)n * 4096 + k0 + kr] = tp_l[n][kr];
        }
    } else {
        // ---- encode: 16 samples ----
        int idx = bx - PREP_BLOCKS;
        int b = idx / ENC_SBLK;
        int s0 = (idx - b * ENC_SBLK) * 16;
        {
            int v = tid >> 4, s = tid & 15;
            int sg = s0 + s;
            xs[v][s] = (sg < SAMPLES) ? x[((size_t)b * NVARS + v) * SAMPLES + sg] : 0.f;
        }
        __syncthreads();
        int d = tid & 127;
        int sh = (tid >> 7) * 8;
        float wv[NVARS];
#pragma unroll
        for (int v = 0; v < NVARS; v++) wv[v] = Ws[v * EMB + d];
        float bias = bs[d];
#pragma unroll
        for (int s = 0; s < 8; s++) {
            int sg = s0 + sh + s;
            float acc = bias;
#pragma unroll
            for (int v = 0; v < NVARS; v++) acc += xs[v][sh + s] * wv[v];
            float val = (sg < SAMPLES) ? floorf(acc) : 0.f;
            g_enc[((size_t)b * SPAD + sg) * EMB + d] = __float2half_rn(val);
        }
    }
}

// ======================= Kernel 2: windowed GEMM (batch-paired, occ 2) =======================
// CTA tile: M=128 (64 tokens of batch b + 64 tokens of batch b+16), N=128; 128 threads.
// Warp grid 2x2, warp tile 64m x 64n. R4-proven schedule:
//   fill(it+1) -> CP_WAIT(1) -> bar -> compute(it) -> bar
// Stage smem: A 16KB + Bhi 16KB + Blo 16KB = 48KB; double buffered; 97KB total
// -> 2 CTAs/SM (53K regs, 195KB smem) so a second MMA stream hides stage bubbles.
// Rows are 128B (8 x 16B chunks), XOR swizzle chunk' = c ^ (row&7).
#define SM_A  1024u
#define SM_BH 17408u
#define SM_BL 33792u
#define STAGE_STRIDE 49152u
#define SMEM_BYTES (1024 + 2 * 49152)

__global__ void __launch_bounds__(128, 2)
gemm_kernel(const float* __restrict__ bp, float* __restrict__ out) {
    extern __shared__ char smem[];
    uint32_t sb = smem_u32(smem);
    int tid = threadIdx.x, wid = tid >> 5, lid = tid & 31;
    int t0 = blockIdx.x * 64;       // 64-token tile
    int b  = blockIdx.y;            // pair (b, b+16)

    ((float*)(smem + 512))[tid] = bp[tid];

    float acc[4][8][4];
#pragma unroll
    for (int i = 0; i < 4; i++)
#pragma unroll
        for (int j = 0; j < 8; j++)
#pragma unroll
            for (int k = 0; k < 4; k++) acc[i][j][k] = 0.f;

    // ---- producer addressing (128 threads; prow in [0,16), pc in [0,8)) ----
    int prow = tid >> 3, pc = tid & 7;
    const __half* aLo = g_enc + ((size_t)b * SPAD + (size_t)t0 * 4) * 128
                        + (size_t)prow * 512 + pc * 8;
    const __half* aHi = aLo + (size_t)16 * SPAD * 128;   // batch b+16
    const __half* bPt = g_wt + (size_t)prow * 4096 + pc * 8;
    uint32_t pdst = (uint32_t)prow * 128 + (uint32_t)((pc ^ (prow & 7)) << 4);

    auto fill = [&](int w2, int buf) {
        uint32_t st = (uint32_t)buf * STAGE_STRIDE;
        size_t off = (size_t)w2 * 64;
#pragma unroll
        for (int r = 0; r < 4; r++)   // A rows 0..63 (batch b): +16 rows = +16 tokens
            CP16(sb + SM_A + st + pdst + r * 2048u, (const void*)(aLo + off + (size_t)r * 8192));
#pragma unroll
        for (int r = 0; r < 4; r++)   // A rows 64..127 (batch b+16)
            CP16(sb + SM_A + st + 8192u + pdst + r * 2048u, (const void*)(aHi + off + (size_t)r * 8192));
#pragma unroll
        for (int r = 0; r < 8; r++)   // B hi: 128 n rows
            CP16(sb + SM_BH + st + pdst + r * 2048u, (const void*)(bPt + off + (size_t)r * 65536));
#pragma unroll
        for (int r = 0; r < 8; r++)   // B lo
            CP16(sb + SM_BL + st + pdst + r * 2048u, (const void*)(bPt + 524288 + off + (size_t)r * 65536));
        CP_COMMIT();
    };

    // ---- consumer addressing (warp tile 64m x 64n; warp grid 2x2) ----
    int wr = wid & 1, wc = wid >> 1;
    uint32_t xorv = (uint32_t)(lid & 7);
    uint32_t aRowOff[4], bRowOff[4];
#pragma unroll
    for (int mi = 0; mi < 4; mi++)
        aRowOff[mi] = (uint32_t)(wr * 64 + mi * 16 + (lid & 15)) * 128;
#pragma unroll
    for (int p = 0; p < 4; p++)
        bRowOff[p] = (uint32_t)(wc * 64 + p * 16 + (lid & 7) + ((lid & 16) ? 8 : 0)) * 128;
    uint32_t cbA = (uint32_t)(lid >> 4);
    uint32_t cbB = (uint32_t)((lid >> 3) & 1);

    auto compute = [&](int buf) {
        uint32_t st = (uint32_t)buf * STAGE_STRIDE;
        uint32_t baseA = sb + SM_A + st, baseBH = sb + SM_BH + st, baseBL = sb + SM_BL + st;
#pragma unroll
        for (int kk = 0; kk < 4; kk++) {
            uint32_t aSw = ((2u * kk + cbA) ^ xorv) << 4;
            uint32_t bSw = ((2u * kk + cbB) ^ xorv) << 4;
            uint32_t afr[4][4];
#pragma unroll
            for (int mi = 0; mi < 4; mi++)
                LDSM4(afr[mi], baseA + aRowOff[mi] + aSw);
            uint32_t bfr[4][4];
#pragma unroll
            for (int p = 0; p < 4; p++)
                LDSM4(bfr[p], baseBH + bRowOff[p] + bSw);
#pragma unroll
            for (int mi = 0; mi < 4; mi++)
#pragma unroll
                for (int p = 0; p < 4; p++) {
                    MMA16816(acc[mi][2 * p],     afr[mi], bfr[p][0], bfr[p][1]);
                    MMA16816(acc[mi][2 * p + 1], afr[mi], bfr[p][2], bfr[p][3]);
                }
#pragma unroll
            for (int p = 0; p < 4; p++)
                LDSM4(bfr[p], baseBL + bRowOff[p] + bSw);
#pragma unroll
            for (int mi = 0; mi < 4; mi++)
#pragma unroll
                for (int p = 0; p < 4; p++) {
                    MMA16816(acc[mi][2 * p],     afr[mi], bfr[p][0], bfr[p][1]);
                    MMA16816(acc[mi][2 * p + 1], afr[mi], bfr[p][2], bfr[p][3]);
                }
        }
    };

    // ---- R4-proven double-buffered loop ----
    fill(0, 0);
    for (int it = 0; it < NST; it++) {
        int buf = it & 1;
        if (it + 1 < NST) {
            fill(it + 1, buf ^ 1);
            CP_WAIT(1);            // stage(it) complete
        } else {
            CP_WAIT(0);
        }
        __syncthreads();
        compute(buf);
        __syncthreads();           // guard buffer reuse
    }

    // ---- epilogue: D + b_patch, floor, fp32 stores ----
    const float* bsm = (const float*)(smem + 512);
    int bOut = b + (wr ? 16 : 0);
    int rloc = lid >> 2;                        // row within the 64-token tile
    int nb = wc * 64 + (lid & 3) * 2;
#pragma unroll
    for (int mi = 0; mi < 4; mi++) {
        int trow0 = t0 + rloc + mi * 16;
#pragma unroll
        for (int ni = 0; ni < 8; ni++) {
            int n = nb + ni * 8;
            float bx = bsm[n], by = bsm[n + 1];
            if (trow0 < NTOK) {
                float2 v;
                v.x = floorf(acc[mi][ni][0] + bx);
                v.y = floorf(acc[mi][ni][1] + by);
                *(float2*)(out + ((size_t)bOut * NTOK + trow0) * 128 + n) = v;
            }
            if (trow0 + 8 < NTOK) {
                float2 v;
                v.x = floorf(acc[mi][ni][2] + bx);
                v.y = floorf(acc[mi][ni][3] + by);
                *(float2*)(out + ((size_t)bOut * NTOK + trow0 + 8) * 128 + n) = v;
            }
        }
    }
}

// ======================= launch =======================
extern "C" void kernel_launch(void* const* d_in, const int* in_sizes, int n_in,
                              void* d_out, int out_size) {
    const float* x  = (const float*)d_in[0];
    const float* Ws = (const float*)d_in[1];
    const float* bs = (const float*)d_in[2];
    const float* Wp = (const float*)d_in[3];
    const float* bp = (const float*)d_in[4];
    float* out = (float*)d_out;

    prep_encode_kernel<<<PREP_BLOCKS + ENC_SBLK * BATCH, 256>>>(x, Ws, bs, Wp);

    cudaFuncSetAttribute(gemm_kernel, cudaFuncAttributeMaxDynamicSharedMemorySize, SMEM_BYTES);
    gemm_kernel<<<dim3(16, 16), 128, SMEM_BYTES>>>(bp, out);

    (void)in_sizes; (void)n_in; (void)out_size;
}